// round 15
// baseline (speedup 1.0000x reference)
#include <cuda_runtime.h>
#include <cuda_fp16.h>
#include <math.h>

#define BATCH  128
#define LSEQ   2048
#define HDIM   512
#define DDIM   512
#define TSTEPS 10
#define NWARP  16
#define SPLITS 16
#define KC     64    // K per split
#define BN     64    // GEMM N tile (32 n-blocks)
#define KB     16    // GEMM k sub-tile

typedef unsigned long long ull;

// Inter-kernel state (allocation-free scratch)
__device__ float g_s[BATCH * HDIM];                 // s / cell state
__device__ float g_h[BATCH * HDIM];                 // hidden state
__device__ float g_x[BATCH * DDIM];                 // next input x
__device__ float g_part[SPLITS * BATCH * 4 * HDIM]; // split-K partials (16MB)
__device__ float g_sqh[BATCH * LSEQ];               // sqrt(sum h^2) per row (1MB)
__device__ __align__(16) __half g_hid16[(size_t)BATCH * LSEQ * HDIM]; // 256MB

// ---- packed f32x2 helpers (Blackwell FFMA2) ----
__device__ __forceinline__ ull pack2(float lo, float hi) {
    ull r; asm("mov.b64 %0, {%1, %2};" : "=l"(r) : "f"(lo), "f"(hi)); return r;
}
__device__ __forceinline__ void unpack2(ull v, float& lo, float& hi) {
    asm("mov.b64 {%0, %1}, %2;" : "=f"(lo), "=f"(hi) : "l"(v));
}
__device__ __forceinline__ ull ffma2(ull a, ull b, ull c) {
    ull d; asm("fma.rn.f32x2 %0, %1, %2, %3;" : "=l"(d) : "l"(a), "l"(b), "l"(c));
    return d;
}

// ---------------------------------------------------------------------------
// Attention step 0: stream fp32 hid_states (2-deep register prefetch),
// cosine-softmax context; write fp16 copy AND g_sqh in the same pass.
// Triggers PDL immediately (gemm(0) reads only kernel inputs).
// ---------------------------------------------------------------------------
struct Row32 { float4 v[4]; };

__device__ __forceinline__ void a0_load(Row32& r, const float4* base, int l, int lane) {
    const float4* hp = base + (size_t)l * (HDIM / 4);
#pragma unroll
    for (int k = 0; k < 4; k++) r.v[k] = hp[lane + 32 * k];
}

__global__ __launch_bounds__(512) void attn0_kernel(
    const float* __restrict__ hid, const float* __restrict__ s_init)
{
    cudaTriggerProgrammaticLaunchCompletion();   // gemm(0) independent of us

    const int b    = blockIdx.x;
    const int lane = threadIdx.x & 31;
    const int wid  = threadIdx.x >> 5;

    const float* s_in = s_init + (size_t)b * HDIM;

    float4 s4[4];
#pragma unroll
    for (int k = 0; k < 4; k++)
        s4[k] = *reinterpret_cast<const float4*>(s_in + 4 * lane + 128 * k);

    float ss = 0.f;
#pragma unroll
    for (int k = 0; k < 4; k++)
        ss += s4[k].x * s4[k].x + s4[k].y * s4[k].y +
              s4[k].z * s4[k].z + s4[k].w * s4[k].w;
#pragma unroll
    for (int off = 16; off; off >>= 1)
        ss += __shfl_xor_sync(0xffffffffu, ss, off);
    const float sqs = sqrtf(ss);

    const float4* base = reinterpret_cast<const float4*>(hid)
                       + (size_t)b * (size_t)LSEQ * (HDIM / 4);
    __half* out16 = g_hid16 + (size_t)b * (size_t)LSEQ * HDIM;
    float* sqh_b  = g_sqh + (size_t)b * LSEQ;

    float4 acc[4];
#pragma unroll
    for (int k = 0; k < 4; k++) acc[k] = make_float4(0.f, 0.f, 0.f, 0.f);
    float Z = 0.f;

    Row32 C0, C1;
    a0_load(C0, base, wid, lane);
    a0_load(C1, base, wid + NWARP, lane);

    for (int j = 0; j < LSEQ / NWARP; j += 2) {
        Row32 N0, N1;
        if (j + 2 < LSEQ / NWARP) a0_load(N0, base, wid + NWARP * (j + 2), lane);
        if (j + 3 < LSEQ / NWARP) a0_load(N1, base, wid + NWARP * (j + 3), lane);

#pragma unroll
        for (int half = 0; half < 2; half++) {
            Row32& R = half ? C1 : C0;
            const int l = wid + NWARP * (j + half);

            float d = 0.f, hs = 0.f;
#pragma unroll
            for (int k = 0; k < 4; k++) {
                d  += s4[k].x * R.v[k].x + s4[k].y * R.v[k].y +
                      s4[k].z * R.v[k].z + s4[k].w * R.v[k].w;
                hs += R.v[k].x * R.v[k].x + R.v[k].y * R.v[k].y +
                      R.v[k].z * R.v[k].z + R.v[k].w * R.v[k].w;
            }
#pragma unroll
            for (int off = 16; off; off >>= 1) {
                d  += __shfl_xor_sync(0xffffffffu, d,  off);
                hs += __shfl_xor_sync(0xffffffffu, hs, off);
            }

#pragma unroll
            for (int k = 0; k < 4; k++) {
                __half2 a = __floats2half2_rn(R.v[k].x, R.v[k].y);
                __half2 c = __floats2half2_rn(R.v[k].z, R.v[k].w);
                uint2 pk;
                pk.x = *reinterpret_cast<unsigned*>(&a);
                pk.y = *reinterpret_cast<unsigned*>(&c);
                *reinterpret_cast<uint2*>(out16 + (size_t)l * HDIM + 128 * k + 4 * lane) = pk;
            }
            const float sqh = sqrtf(hs);
            if (lane == 0) sqh_b[l] = sqh;

            const float denom = sqh * sqs + 1e-8f;
            const float w = __expf(d / denom);
            Z += w;
#pragma unroll
            for (int k = 0; k < 4; k++) {
                acc[k].x += w * R.v[k].x; acc[k].y += w * R.v[k].y;
                acc[k].z += w * R.v[k].z; acc[k].w += w * R.v[k].w;
            }
        }
        C0 = N0; C1 = N1;
    }

    __shared__ float sacc[NWARP][HDIM];
    __shared__ float sZ[NWARP];
#pragma unroll
    for (int k = 0; k < 4; k++)
        *reinterpret_cast<float4*>(&sacc[wid][4 * lane + 128 * k]) = acc[k];
    if (lane == 0) sZ[wid] = Z;
    __syncthreads();

    const int col = threadIdx.x;
    float cs = 0.f;
#pragma unroll
    for (int w2 = 0; w2 < NWARP; w2++) cs += sacc[w2][col];
    float Zt = 0.f;
#pragma unroll
    for (int w2 = 0; w2 < NWARP; w2++) Zt += sZ[w2];

    g_s[(size_t)b * HDIM + col] = s_in[col] + cs / Zt;
}

// ---------------------------------------------------------------------------
// Combine prologue (device fn): gather split-K partials -> LSTM -> MLP head
// -> scatter output for step tprev. Writes g_h/g_x globals; c into srow smem
// (if non-null). 512 threads. g_s NOT written.
// ---------------------------------------------------------------------------
__device__ __forceinline__ void combine_body(
    int b, int tid, int tprev,
    const float* __restrict__ b_lstm,
    const float* __restrict__ W1, const float* __restrict__ b1,
    const float* __restrict__ W2, const float* __restrict__ b2,
    float* __restrict__ out,
    float* gates, float* hrow, float* apart /*8*64*/, float* a_s,
    float* srow)
{
    {
        float4 v = reinterpret_cast<const float4*>(b_lstm)[tid];
#pragma unroll
        for (int sp = 0; sp < SPLITS; sp++) {
            const float4* p = reinterpret_cast<const float4*>(
                g_part + ((size_t)sp * BATCH + b) * (4 * HDIM));
            float4 u = p[tid];
            v.x += u.x; v.y += u.y; v.z += u.z; v.w += u.w;
        }
        reinterpret_cast<float4*>(gates)[tid] = v;
    }
    __syncthreads();

    {
        const int ch = tid;
        const float gi = gates[ch];
        const float gf = gates[512 + ch];
        const float gg = gates[1024 + ch];
        const float go = gates[1536 + ch];

        const float sv = g_s[(size_t)b * HDIM + ch];
        const float si = 1.f / (1.f + expf(-gi));
        const float sf = 1.f / (1.f + expf(-gf));
        const float so = 1.f / (1.f + expf(-go));
        const float cv = sf * sv + si * tanhf(gg);
        const float hv = so * tanhf(cv);
        if (srow) srow[ch] = cv;
        hrow[ch] = hv;
        g_h[(size_t)b * HDIM + ch] = hv;
    }
    __syncthreads();

    {
        const int j   = tid & 63;
        const int seg = tid >> 6;
        float p = 0.f;
        const float* w = W1 + (size_t)(seg * 64) * 64 + j;
#pragma unroll 8
        for (int kk = 0; kk < 64; kk++)
            p += hrow[seg * 64 + kk] * w[(size_t)kk * 64];
        apart[seg * 64 + j] = p;
    }
    __syncthreads();
    if (tid < 64) {
        float v = b1[tid];
#pragma unroll
        for (int s2 = 0; s2 < 8; s2++) v += apart[s2 * 64 + tid];
        a_s[tid] = (v > 0.f) ? v : 0.01f * v;
    }
    __syncthreads();

    {
        const int d = tid;
        float v = b2[d];
#pragma unroll 8
        for (int j = 0; j < 64; j++)
            v += a_s[j] * W2[(size_t)j * 512 + d];

        g_x[(size_t)b * DDIM + d] = v;

        const int k  = tprev * DDIM + d;
        const int ii = k / 10;
        const int jj = k - 10 * ii;
        out[((size_t)b * TSTEPS + jj) * 512 + ii] = v;
    }
    __syncthreads();
}

// ---------------------------------------------------------------------------
// Fused combine(t-1) + attention(t) for steps 1..9. PDL trigger fires right
// after the prologue so gemm(t) can start while attention bodies run.
// ---------------------------------------------------------------------------
struct Pair16 { uint4 c[4]; float2 q; };

__device__ __forceinline__ void a16_load(Pair16& P, const uint4* base,
                                         const float* sqh_b, int p, int lane) {
    const uint4* rp = base + (size_t)(2 * p) * (HDIM / 8);
    P.c[0] = rp[lane];       P.c[1] = rp[lane + 32];
    P.c[2] = rp[64 + lane];  P.c[3] = rp[64 + lane + 32];
    P.q = *reinterpret_cast<const float2*>(sqh_b + 2 * p);
}

__device__ __forceinline__ void a16_proc(const Pair16& P, const ull* s2,
                                         ull* acc2, float& Z, float sqs) {
    ull hA[8], hB[8];
    {
        const __half2* pa = reinterpret_cast<const __half2*>(&P.c[0]);
#pragma unroll
        for (int q = 0; q < 4; q++) { float2 f = __half22float2(pa[q]); hA[q] = pack2(f.x, f.y); }
        pa = reinterpret_cast<const __half2*>(&P.c[1]);
#pragma unroll
        for (int q = 0; q < 4; q++) { float2 f = __half22float2(pa[q]); hA[4+q] = pack2(f.x, f.y); }
        const __half2* pb = reinterpret_cast<const __half2*>(&P.c[2]);
#pragma unroll
        for (int q = 0; q < 4; q++) { float2 f = __half22float2(pb[q]); hB[q] = pack2(f.x, f.y); }
        pb = reinterpret_cast<const __half2*>(&P.c[3]);
#pragma unroll
        for (int q = 0; q < 4; q++) { float2 f = __half22float2(pb[q]); hB[4+q] = pack2(f.x, f.y); }
    }

    ull d2A = 0ull, d2B = 0ull;
#pragma unroll
    for (int k = 0; k < 8; k++) {
        d2A = ffma2(s2[k], hA[k], d2A);
        d2B = ffma2(s2[k], hB[k], d2B);
    }
    float aL, aH, bL, bH;
    unpack2(d2A, aL, aH); unpack2(d2B, bL, bH);
    float dA = aL + aH, dB = bL + bH;
#pragma unroll
    for (int off = 16; off; off >>= 1) {
        dA += __shfl_xor_sync(0xffffffffu, dA, off);
        dB += __shfl_xor_sync(0xffffffffu, dB, off);
    }

    const float wA = __expf(__fdividef(dA, P.q.x * sqs + 1e-8f));
    const float wB = __expf(__fdividef(dB, P.q.y * sqs + 1e-8f));
    Z += wA + wB;
    const ull w2A = pack2(wA, wA);
    const ull w2B = pack2(wB, wB);
#pragma unroll
    for (int k = 0; k < 8; k++) {
        acc2[k] = ffma2(w2A, hA[k], acc2[k]);
        acc2[k] = ffma2(w2B, hB[k], acc2[k]);
    }
}

__global__ __launch_bounds__(512) void attnC16_kernel(
    const float* __restrict__ b_lstm,
    const float* __restrict__ W1, const float* __restrict__ b1,
    const float* __restrict__ W2, const float* __restrict__ b2,
    float* __restrict__ out, int t)
{
    __shared__ float gates[4 * HDIM];
    __shared__ float hrow[HDIM];
    __shared__ float apart[8 * 64];
    __shared__ float a_s[64];
    __shared__ float srow[HDIM];
    __shared__ float sacc[NWARP][HDIM];
    __shared__ float sZ[NWARP];

    const int b    = blockIdx.x;
    const int tid  = threadIdx.x;
    const int lane = tid & 31;
    const int wid  = tid >> 5;

    combine_body(b, tid, t - 1, b_lstm, W1, b1, W2, b2, out,
                 gates, hrow, apart, a_s, srow);

    // prologue outputs (g_x, g_h) are globally visible -> release gemm(t)
    __threadfence();
    cudaTriggerProgrammaticLaunchCompletion();

    const float* s_in = srow;

    float sv[16];
#pragma unroll
    for (int k = 0; k < 2; k++) {
        float4 a = *reinterpret_cast<const float4*>(s_in + 256 * k + 8 * lane);
        float4 c = *reinterpret_cast<const float4*>(s_in + 256 * k + 8 * lane + 4);
        sv[8*k+0]=a.x; sv[8*k+1]=a.y; sv[8*k+2]=a.z; sv[8*k+3]=a.w;
        sv[8*k+4]=c.x; sv[8*k+5]=c.y; sv[8*k+6]=c.z; sv[8*k+7]=c.w;
    }
    float ss = 0.f;
#pragma unroll
    for (int k = 0; k < 16; k++) ss += sv[k] * sv[k];
#pragma unroll
    for (int off = 16; off; off >>= 1)
        ss += __shfl_xor_sync(0xffffffffu, ss, off);
    const float sqs = sqrtf(ss);

    ull s2[8];
#pragma unroll
    for (int k = 0; k < 8; k++) s2[k] = pack2(sv[2*k], sv[2*k+1]);

    const uint4* base = reinterpret_cast<const uint4*>(g_hid16)
                      + (size_t)b * (size_t)LSEQ * (HDIM / 8);
    const float* sqh_b = g_sqh + (size_t)b * LSEQ;

    ull acc2[8];
#pragma unroll
    for (int k = 0; k < 8; k++) acc2[k] = 0ull;
    float Z = 0.f;

    const int NP = LSEQ / 32;
    Pair16 C0, C1;
    a16_load(C0, base, sqh_b, wid, lane);
    a16_load(C1, base, sqh_b, wid + 16, lane);

    for (int j = 0; j < NP; j += 2) {
        Pair16 N0, N1;
        if (j + 2 < NP) a16_load(N0, base, sqh_b, wid + 16 * (j + 2), lane);
        if (j + 3 < NP) a16_load(N1, base, sqh_b, wid + 16 * (j + 3), lane);

        a16_proc(C0, s2, acc2, Z, sqs);
        a16_proc(C1, s2, acc2, Z, sqs);

        C0 = N0; C1 = N1;
    }

#pragma unroll
    for (int k = 0; k < 8; k++) {
        float lo, hi;
        unpack2(acc2[k], lo, hi);
        const int idx = (k < 4) ? (8 * lane + 2 * k) : (256 + 8 * lane + 2 * (k - 4));
        sacc[wid][idx]     = lo;
        sacc[wid][idx + 1] = hi;
    }
    if (lane == 0) sZ[wid] = Z;
    __syncthreads();

    const int col = tid;
    float cs = 0.f;
#pragma unroll
    for (int w2 = 0; w2 < NWARP; w2++) cs += sacc[w2][col];
    float Zt = 0.f;
#pragma unroll
    for (int w2 = 0; w2 < NWARP; w2++) Zt += sZ[w2];

    g_s[(size_t)b * HDIM + col] = srow[col] + cs / Zt;
}

// ---------------------------------------------------------------------------
// Tail: combine(TSTEPS-1) only (final output scatter).
// ---------------------------------------------------------------------------
__global__ __launch_bounds__(512) void combine_tail(
    const float* __restrict__ b_lstm,
    const float* __restrict__ W1, const float* __restrict__ b1,
    const float* __restrict__ W2, const float* __restrict__ b2,
    float* __restrict__ out)
{
    __shared__ float gates[4 * HDIM];
    __shared__ float hrow[HDIM];
    __shared__ float apart[8 * 64];
    __shared__ float a_s[64];

    combine_body(blockIdx.x, threadIdx.x, TSTEPS - 1,
                 b_lstm, W1, b1, W2, b2, out,
                 gates, hrow, apart, a_s, nullptr);
}

// ---------------------------------------------------------------------------
// Gates GEMM, split-K, 256-thread CTAs for 4-CTA/SM occupancy.
// Grid (32 n-blocks, 16 k-splits) = 512 CTAs. Thread (tx=tid&7, ty=tid>>3):
// rows ty*4..+3, cols tx*8..+7. Same per-output K-chain as before.
// ---------------------------------------------------------------------------
#define AP 132

__global__ __launch_bounds__(256) void gemm_kernel(
    const float* __restrict__ W_ih, const float* __restrict__ W_hh,
    const float* __restrict__ x0, const float* __restrict__ h0, int t)
{
    cudaGridDependencySynchronize();

    const int n0  = blockIdx.x * BN;     // 64-wide n tile
    const int sp  = blockIdx.y;
    const int kg0 = sp * KC;
    const bool isX = (kg0 < 512);
    const float* A = isX ? ((t == 0) ? x0 : g_x) : ((t == 0) ? h0 : g_h);
    const float* W = isX ? W_ih : W_hh;
    const int ka0 = isX ? kg0 : (kg0 - 512);

    __shared__ float As[KB][AP];    // 16 x 132 (~8.4KB)
    __shared__ float Bs[KB][BN];    // 16 x 64  (4KB)

    const int tid = threadIdx.x;
    const int tx  = tid & 7;        // 0..7  -> cols tx*8..+7
    const int ty  = tid >> 3;       // 0..31 -> rows ty*4..+3

    ull acc2[4][4];
#pragma unroll
    for (int i = 0; i < 4; i++)
#pragma unroll
        for (int j = 0; j < 4; j++) acc2[i][j] = 0ull;

    for (int kb = 0; kb < KC; kb += KB) {
        {   // A tile: 128 x 16 transposed; 2 float4 per thread
            const int m  = tid >> 1;
            const int ko = (tid & 1) * 8;
            const float* ap = A + (size_t)m * 512 + ka0 + kb + ko;
            float4 v0 = *reinterpret_cast<const float4*>(ap);
            float4 v1 = *reinterpret_cast<const float4*>(ap + 4);
            As[ko+0][m] = v0.x; As[ko+1][m] = v0.y;
            As[ko+2][m] = v0.z; As[ko+3][m] = v0.w;
            As[ko+4][m] = v1.x; As[ko+5][m] = v1.y;
            As[ko+6][m] = v1.z; As[ko+7][m] = v1.w;
        }
        {   // B tile: 16 x 64; one float4 per thread
            const int kk = tid >> 4;
            const int c  = (tid & 15) * 4;
            *reinterpret_cast<float4*>(&Bs[kk][c]) =
                *reinterpret_cast<const float4*>(
                    W + (size_t)(ka0 + kb + kk) * (4 * HDIM) + n0 + c);
        }
        __syncthreads();

#pragma unroll
        for (int kk = 0; kk < KB; kk++) {
            float a[4];
            *reinterpret_cast<float4*>(a) =
                *reinterpret_cast<float4*>(&As[kk][ty * 4]);
            ulonglong2 b01 = *reinterpret_cast<ulonglong2*>(&Bs[kk][tx * 8]);
            ulonglong2 b23 = *reinterpret_cast<ulonglong2*>(&Bs[kk][tx * 8 + 4]);
#pragma unroll
            for (int i = 0; i < 4; i++) {
                const ull ai = pack2(a[i], a[i]);
                acc2[i][0] = ffma2(ai, b01.x, acc2[i][0]);
                acc2[i][1] = ffma2(ai, b01.y, acc2[i][1]);
                acc2[i][2] = ffma2(ai, b23.x, acc2[i][2]);
                acc2[i][3] = ffma2(ai, b23.y, acc2[i][3]);
            }
        }
        __syncthreads();
    }

    float* P = g_part + (size_t)sp * BATCH * (4 * HDIM);
#pragma unroll
    for (int i = 0; i < 4; i++) {
        const int m = ty * 4 + i;
        ulonglong2 w0; w0.x = acc2[i][0]; w0.y = acc2[i][1];
        ulonglong2 w1; w1.x = acc2[i][2]; w1.y = acc2[i][3];
        *reinterpret_cast<ulonglong2*>(&P[(size_t)m * (4*HDIM) + n0 + tx*8])     = w0;
        *reinterpret_cast<ulonglong2*>(&P[(size_t)m * (4*HDIM) + n0 + tx*8 + 4]) = w1;
    }
}

// ---------------------------------------------------------------------------
static void launch_gemm_pdl(const float* W_ih, const float* W_hh,
                            const float* x0, const float* h0, int t)
{
    cudaLaunchAttribute attrs[1];
    attrs[0].id = cudaLaunchAttributeProgrammaticStreamSerialization;
    attrs[0].val.programmaticStreamSerializationAllowed = 1;

    cudaLaunchConfig_t cfg = {};
    cfg.gridDim  = dim3(32, SPLITS);
    cfg.blockDim = dim3(256);
    cfg.dynamicSmemBytes = 0;
    cfg.stream = 0;
    cfg.attrs = attrs;
    cfg.numAttrs = 1;

    cudaLaunchKernelEx(&cfg, gemm_kernel, W_ih, W_hh, x0, h0, t);
}

extern "C" void kernel_launch(void* const* d_in, const int* in_sizes, int n_in,
                              void* d_out, int out_size)
{
    const float* batch  = (const float*)d_in[0];
    const float* hid    = (const float*)d_in[1];
    const float* h0     = (const float*)d_in[2];
    const float* s0     = (const float*)d_in[3];
    const float* W_ih   = (const float*)d_in[4];
    const float* W_hh   = (const float*)d_in[5];
    const float* b_lstm = (const float*)d_in[6];
    const float* W1     = (const float*)d_in[7];
    const float* b1     = (const float*)d_in[8];
    const float* W2     = (const float*)d_in[9];
    const float* b2     = (const float*)d_in[10];
    float* out = (float*)d_out;

    attn0_kernel<<<BATCH, 512>>>(hid, s0);
    launch_gemm_pdl(W_ih, W_hh, batch, h0, 0);

    for (int t = 1; t < TSTEPS; t++) {
        attnC16_kernel<<<BATCH, 512>>>(b_lstm, W1, b1, W2, b2, out, t);
        launch_gemm_pdl(W_ih, W_hh, batch, h0, t);
    }

    combine_tail<<<BATCH, 512>>>(b_lstm, W1, b1, W2, b2, out);
}

// round 16
// speedup vs baseline: 1.1957x; 1.1957x over previous
#include <cuda_runtime.h>
#include <cuda_fp16.h>
#include <math.h>

#define BATCH  128
#define LSEQ   2048
#define HDIM   512
#define DDIM   512
#define TSTEPS 10
#define NWARP  16
#define SPLITS 16
#define KC     64    // K per split
#define BN     128   // GEMM N tile
#define KB     16    // GEMM k sub-tile

typedef unsigned long long ull;

// Inter-kernel state (allocation-free scratch)
__device__ float g_s[BATCH * HDIM];                 // s / cell state
__device__ float g_h[BATCH * HDIM];                 // hidden state
__device__ float g_x[BATCH * DDIM];                 // next input x
__device__ float g_part[SPLITS * BATCH * 4 * HDIM]; // split-K partials (16MB)
__device__ float g_sqh[BATCH * LSEQ];               // sqrt(sum h^2) per row (1MB)
__device__ __align__(16) __half g_hid16[(size_t)BATCH * LSEQ * HDIM]; // 256MB

// ---- packed f32x2 helpers (Blackwell FFMA2) ----
__device__ __forceinline__ ull pack2(float lo, float hi) {
    ull r; asm("mov.b64 %0, {%1, %2};" : "=l"(r) : "f"(lo), "f"(hi)); return r;
}
__device__ __forceinline__ void unpack2(ull v, float& lo, float& hi) {
    asm("mov.b64 {%0, %1}, %2;" : "=f"(lo), "=f"(hi) : "l"(v));
}
__device__ __forceinline__ ull ffma2(ull a, ull b, ull c) {
    ull d; asm("fma.rn.f32x2 %0, %1, %2, %3;" : "=l"(d) : "l"(a), "l"(b), "l"(c));
    return d;
}

// ---------------------------------------------------------------------------
// Attention step 0: stream fp32 hid_states (2-deep register prefetch, __ldcs
// streaming reads), cosine-softmax context; write fp16 copy (__stcs) AND
// g_sqh in the same pass. Triggers PDL immediately.
// ---------------------------------------------------------------------------
struct Row32 { float4 v[4]; };

__device__ __forceinline__ void a0_load(Row32& r, const float4* base, int l, int lane) {
    const float4* hp = base + (size_t)l * (HDIM / 4);
#pragma unroll
    for (int k = 0; k < 4; k++) r.v[k] = __ldcs(hp + lane + 32 * k);
}

__global__ __launch_bounds__(512) void attn0_kernel(
    const float* __restrict__ hid, const float* __restrict__ s_init)
{
    cudaTriggerProgrammaticLaunchCompletion();   // gemm(0) independent of us

    const int b    = blockIdx.x;
    const int lane = threadIdx.x & 31;
    const int wid  = threadIdx.x >> 5;

    const float* s_in = s_init + (size_t)b * HDIM;

    float4 s4[4];
#pragma unroll
    for (int k = 0; k < 4; k++)
        s4[k] = *reinterpret_cast<const float4*>(s_in + 4 * lane + 128 * k);

    float ss = 0.f;
#pragma unroll
    for (int k = 0; k < 4; k++)
        ss += s4[k].x * s4[k].x + s4[k].y * s4[k].y +
              s4[k].z * s4[k].z + s4[k].w * s4[k].w;
#pragma unroll
    for (int off = 16; off; off >>= 1)
        ss += __shfl_xor_sync(0xffffffffu, ss, off);
    const float sqs = sqrtf(ss);

    const float4* base = reinterpret_cast<const float4*>(hid)
                       + (size_t)b * (size_t)LSEQ * (HDIM / 4);
    __half* out16 = g_hid16 + (size_t)b * (size_t)LSEQ * HDIM;
    float* sqh_b  = g_sqh + (size_t)b * LSEQ;

    float4 acc[4];
#pragma unroll
    for (int k = 0; k < 4; k++) acc[k] = make_float4(0.f, 0.f, 0.f, 0.f);
    float Z = 0.f;

    Row32 C0, C1;
    a0_load(C0, base, wid, lane);
    a0_load(C1, base, wid + NWARP, lane);

    for (int j = 0; j < LSEQ / NWARP; j += 2) {
        Row32 N0, N1;
        if (j + 2 < LSEQ / NWARP) a0_load(N0, base, wid + NWARP * (j + 2), lane);
        if (j + 3 < LSEQ / NWARP) a0_load(N1, base, wid + NWARP * (j + 3), lane);

#pragma unroll
        for (int half = 0; half < 2; half++) {
            Row32& R = half ? C1 : C0;
            const int l = wid + NWARP * (j + half);

            float d = 0.f, hs = 0.f;
#pragma unroll
            for (int k = 0; k < 4; k++) {
                d  += s4[k].x * R.v[k].x + s4[k].y * R.v[k].y +
                      s4[k].z * R.v[k].z + s4[k].w * R.v[k].w;
                hs += R.v[k].x * R.v[k].x + R.v[k].y * R.v[k].y +
                      R.v[k].z * R.v[k].z + R.v[k].w * R.v[k].w;
            }
#pragma unroll
            for (int off = 16; off; off >>= 1) {
                d  += __shfl_xor_sync(0xffffffffu, d,  off);
                hs += __shfl_xor_sync(0xffffffffu, hs, off);
            }

#pragma unroll
            for (int k = 0; k < 4; k++) {
                __half2 a = __floats2half2_rn(R.v[k].x, R.v[k].y);
                __half2 c = __floats2half2_rn(R.v[k].z, R.v[k].w);
                uint2 pk;
                pk.x = *reinterpret_cast<unsigned*>(&a);
                pk.y = *reinterpret_cast<unsigned*>(&c);
                __stcs(reinterpret_cast<uint2*>(out16 + (size_t)l * HDIM + 128 * k + 4 * lane), pk);
            }
            const float sqh = sqrtf(hs);
            if (lane == 0) sqh_b[l] = sqh;

            const float denom = sqh * sqs + 1e-8f;
            const float w = __expf(d / denom);
            Z += w;
#pragma unroll
            for (int k = 0; k < 4; k++) {
                acc[k].x += w * R.v[k].x; acc[k].y += w * R.v[k].y;
                acc[k].z += w * R.v[k].z; acc[k].w += w * R.v[k].w;
            }
        }
        C0 = N0; C1 = N1;
    }

    __shared__ float sacc[NWARP][HDIM];
    __shared__ float sZ[NWARP];
#pragma unroll
    for (int k = 0; k < 4; k++)
        *reinterpret_cast<float4*>(&sacc[wid][4 * lane + 128 * k]) = acc[k];
    if (lane == 0) sZ[wid] = Z;
    __syncthreads();

    const int col = threadIdx.x;
    float cs = 0.f;
#pragma unroll
    for (int w2 = 0; w2 < NWARP; w2++) cs += sacc[w2][col];
    float Zt = 0.f;
#pragma unroll
    for (int w2 = 0; w2 < NWARP; w2++) Zt += sZ[w2];

    g_s[(size_t)b * HDIM + col] = s_in[col] + cs / Zt;
}

// ---------------------------------------------------------------------------
// Combine prologue: gather split-K partials -> LSTM -> MLP head -> scatter
// output for step tprev. Writes g_h/g_x; c into srow smem. 512 threads.
// ---------------------------------------------------------------------------
__device__ __forceinline__ void combine_body(
    int b, int tid, int tprev,
    const float* __restrict__ b_lstm,
    const float* __restrict__ W1, const float* __restrict__ b1,
    const float* __restrict__ W2, const float* __restrict__ b2,
    float* __restrict__ out,
    float* gates, float* hrow, float* apart /*8*64*/, float* a_s,
    float* srow)
{
    {
        float4 v = reinterpret_cast<const float4*>(b_lstm)[tid];
#pragma unroll
        for (int sp = 0; sp < SPLITS; sp++) {
            const float4* p = reinterpret_cast<const float4*>(
                g_part + ((size_t)sp * BATCH + b) * (4 * HDIM));
            float4 u = p[tid];
            v.x += u.x; v.y += u.y; v.z += u.z; v.w += u.w;
        }
        reinterpret_cast<float4*>(gates)[tid] = v;
    }
    __syncthreads();

    {
        const int ch = tid;
        const float gi = gates[ch];
        const float gf = gates[512 + ch];
        const float gg = gates[1024 + ch];
        const float go = gates[1536 + ch];

        const float sv = g_s[(size_t)b * HDIM + ch];
        const float si = 1.f / (1.f + expf(-gi));
        const float sf = 1.f / (1.f + expf(-gf));
        const float so = 1.f / (1.f + expf(-go));
        const float cv = sf * sv + si * tanhf(gg);
        const float hv = so * tanhf(cv);
        if (srow) srow[ch] = cv;
        hrow[ch] = hv;
        g_h[(size_t)b * HDIM + ch] = hv;
    }
    __syncthreads();

    {
        const int j   = tid & 63;
        const int seg = tid >> 6;
        float p = 0.f;
        const float* w = W1 + (size_t)(seg * 64) * 64 + j;
#pragma unroll 8
        for (int kk = 0; kk < 64; kk++)
            p += hrow[seg * 64 + kk] * w[(size_t)kk * 64];
        apart[seg * 64 + j] = p;
    }
    __syncthreads();
    if (tid < 64) {
        float v = b1[tid];
#pragma unroll
        for (int s2 = 0; s2 < 8; s2++) v += apart[s2 * 64 + tid];
        a_s[tid] = (v > 0.f) ? v : 0.01f * v;
    }
    __syncthreads();

    {
        const int d = tid;
        float v = b2[d];
#pragma unroll 8
        for (int j = 0; j < 64; j++)
            v += a_s[j] * W2[(size_t)j * 512 + d];

        g_x[(size_t)b * DDIM + d] = v;

        const int k  = tprev * DDIM + d;
        const int ii = k / 10;
        const int jj = k - 10 * ii;
        out[((size_t)b * TSTEPS + jj) * 512 + ii] = v;
    }
    __syncthreads();
}

// ---------------------------------------------------------------------------
// Fused combine(t-1) + attention(t) for steps 1..9. PDL trigger after the
// prologue. fp16 stream uses __ldcs (zero intra-step reuse, spare L2).
// ---------------------------------------------------------------------------
struct Pair16 { uint4 c[4]; float2 q; };

__device__ __forceinline__ void a16_load(Pair16& P, const uint4* base,
                                         const float* sqh_b, int p, int lane) {
    const uint4* rp = base + (size_t)(2 * p) * (HDIM / 8);
    P.c[0] = __ldcs(rp + lane);       P.c[1] = __ldcs(rp + lane + 32);
    P.c[2] = __ldcs(rp + 64 + lane);  P.c[3] = __ldcs(rp + 64 + lane + 32);
    P.q = *reinterpret_cast<const float2*>(sqh_b + 2 * p);
}

__device__ __forceinline__ void a16_proc(const Pair16& P, const ull* s2,
                                         ull* acc2, float& Z, float sqs) {
    ull hA[8], hB[8];
    {
        const __half2* pa = reinterpret_cast<const __half2*>(&P.c[0]);
#pragma unroll
        for (int q = 0; q < 4; q++) { float2 f = __half22float2(pa[q]); hA[q] = pack2(f.x, f.y); }
        pa = reinterpret_cast<const __half2*>(&P.c[1]);
#pragma unroll
        for (int q = 0; q < 4; q++) { float2 f = __half22float2(pa[q]); hA[4+q] = pack2(f.x, f.y); }
        const __half2* pb = reinterpret_cast<const __half2*>(&P.c[2]);
#pragma unroll
        for (int q = 0; q < 4; q++) { float2 f = __half22float2(pb[q]); hB[q] = pack2(f.x, f.y); }
        pb = reinterpret_cast<const __half2*>(&P.c[3]);
#pragma unroll
        for (int q = 0; q < 4; q++) { float2 f = __half22float2(pb[q]); hB[4+q] = pack2(f.x, f.y); }
    }

    ull d2A = 0ull, d2B = 0ull;
#pragma unroll
    for (int k = 0; k < 8; k++) {
        d2A = ffma2(s2[k], hA[k], d2A);
        d2B = ffma2(s2[k], hB[k], d2B);
    }
    float aL, aH, bL, bH;
    unpack2(d2A, aL, aH); unpack2(d2B, bL, bH);
    float dA = aL + aH, dB = bL + bH;
#pragma unroll
    for (int off = 16; off; off >>= 1) {
        dA += __shfl_xor_sync(0xffffffffu, dA, off);
        dB += __shfl_xor_sync(0xffffffffu, dB, off);
    }

    const float wA = __expf(__fdividef(dA, P.q.x * sqs + 1e-8f));
    const float wB = __expf(__fdividef(dB, P.q.y * sqs + 1e-8f));
    Z += wA + wB;
    const ull w2A = pack2(wA, wA);
    const ull w2B = pack2(wB, wB);
#pragma unroll
    for (int k = 0; k < 8; k++) {
        acc2[k] = ffma2(w2A, hA[k], acc2[k]);
        acc2[k] = ffma2(w2B, hB[k], acc2[k]);
    }
}

__global__ __launch_bounds__(512) void attnC16_kernel(
    const float* __restrict__ b_lstm,
    const float* __restrict__ W1, const float* __restrict__ b1,
    const float* __restrict__ W2, const float* __restrict__ b2,
    float* __restrict__ out, int t)
{
    __shared__ float gates[4 * HDIM];
    __shared__ float hrow[HDIM];
    __shared__ float apart[8 * 64];
    __shared__ float a_s[64];
    __shared__ float srow[HDIM];
    __shared__ float sacc[NWARP][HDIM];
    __shared__ float sZ[NWARP];

    const int b    = blockIdx.x;
    const int tid  = threadIdx.x;
    const int lane = tid & 31;
    const int wid  = tid >> 5;

    combine_body(b, tid, t - 1, b_lstm, W1, b1, W2, b2, out,
                 gates, hrow, apart, a_s, srow);

    // prologue outputs (g_x, g_h) are globally visible -> release gemm(t)
    __threadfence();
    cudaTriggerProgrammaticLaunchCompletion();

    const float* s_in = srow;

    float sv[16];
#pragma unroll
    for (int k = 0; k < 2; k++) {
        float4 a = *reinterpret_cast<const float4*>(s_in + 256 * k + 8 * lane);
        float4 c = *reinterpret_cast<const float4*>(s_in + 256 * k + 8 * lane + 4);
        sv[8*k+0]=a.x; sv[8*k+1]=a.y; sv[8*k+2]=a.z; sv[8*k+3]=a.w;
        sv[8*k+4]=c.x; sv[8*k+5]=c.y; sv[8*k+6]=c.z; sv[8*k+7]=c.w;
    }
    float ss = 0.f;
#pragma unroll
    for (int k = 0; k < 16; k++) ss += sv[k] * sv[k];
#pragma unroll
    for (int off = 16; off; off >>= 1)
        ss += __shfl_xor_sync(0xffffffffu, ss, off);
    const float sqs = sqrtf(ss);

    ull s2[8];
#pragma unroll
    for (int k = 0; k < 8; k++) s2[k] = pack2(sv[2*k], sv[2*k+1]);

    const uint4* base = reinterpret_cast<const uint4*>(g_hid16)
                      + (size_t)b * (size_t)LSEQ * (HDIM / 8);
    const float* sqh_b = g_sqh + (size_t)b * LSEQ;

    ull acc2[8];
#pragma unroll
    for (int k = 0; k < 8; k++) acc2[k] = 0ull;
    float Z = 0.f;

    const int NP = LSEQ / 32;
    Pair16 C0, C1;
    a16_load(C0, base, sqh_b, wid, lane);
    a16_load(C1, base, sqh_b, wid + 16, lane);

    for (int j = 0; j < NP; j += 2) {
        Pair16 N0, N1;
        if (j + 2 < NP) a16_load(N0, base, sqh_b, wid + 16 * (j + 2), lane);
        if (j + 3 < NP) a16_load(N1, base, sqh_b, wid + 16 * (j + 3), lane);

        a16_proc(C0, s2, acc2, Z, sqs);
        a16_proc(C1, s2, acc2, Z, sqs);

        C0 = N0; C1 = N1;
    }

#pragma unroll
    for (int k = 0; k < 8; k++) {
        float lo, hi;
        unpack2(acc2[k], lo, hi);
        const int idx = (k < 4) ? (8 * lane + 2 * k) : (256 + 8 * lane + 2 * (k - 4));
        sacc[wid][idx]     = lo;
        sacc[wid][idx + 1] = hi;
    }
    if (lane == 0) sZ[wid] = Z;
    __syncthreads();

    const int col = tid;
    float cs = 0.f;
#pragma unroll
    for (int w2 = 0; w2 < NWARP; w2++) cs += sacc[w2][col];
    float Zt = 0.f;
#pragma unroll
    for (int w2 = 0; w2 < NWARP; w2++) Zt += sZ[w2];

    g_s[(size_t)b * HDIM + col] = srow[col] + cs / Zt;
}

// ---------------------------------------------------------------------------
// Tail: combine(TSTEPS-1) only (final output scatter).
// ---------------------------------------------------------------------------
__global__ __launch_bounds__(512) void combine_tail(
    const float* __restrict__ b_lstm,
    const float* __restrict__ W1, const float* __restrict__ b1,
    const float* __restrict__ W2, const float* __restrict__ b2,
    float* __restrict__ out)
{
    __shared__ float gates[4 * HDIM];
    __shared__ float hrow[HDIM];
    __shared__ float apart[8 * 64];
    __shared__ float a_s[64];

    combine_body(blockIdx.x, threadIdx.x, TSTEPS - 1,
                 b_lstm, W1, b1, W2, b2, out,
                 gates, hrow, apart, a_s, nullptr);
}

// ---------------------------------------------------------------------------
// Gates GEMM, split-K — ROUND-8 SHAPE (measured best: 21.9us): 256 threads,
// BN=128, 8x8 micro-tile, FFMA2. PDL griddepsync at entry.
// Grid (16 n-blocks, 16 k-splits) = 256 CTAs.
// ---------------------------------------------------------------------------
__global__ __launch_bounds__(256) void gemm_kernel(
    const float* __restrict__ W_ih, const float* __restrict__ W_hh,
    const float* __restrict__ x0, const float* __restrict__ h0, int t)
{
    cudaGridDependencySynchronize();

    const int n0  = blockIdx.x * BN;
    const int sp  = blockIdx.y;
    const int kg0 = sp * KC;
    const bool isX = (kg0 < 512);
    const float* A = isX ? ((t == 0) ? x0 : g_x) : ((t == 0) ? h0 : g_h);
    const float* W = isX ? W_ih : W_hh;
    const int ka0 = isX ? kg0 : (kg0 - 512);

    __shared__ float As[KB][128];
    __shared__ float Bs[KB][BN];

    const int tid = threadIdx.x;
    const int tx  = tid & 15;
    const int ty  = tid >> 4;

    ull acc2[8][4];
#pragma unroll
    for (int i = 0; i < 8; i++)
#pragma unroll
        for (int j = 0; j < 4; j++) acc2[i][j] = 0ull;

    for (int kb = 0; kb < KC; kb += KB) {
        {
            const int m  = tid >> 1;
            const int ko = (tid & 1) * 8;
            const float* ap = A + (size_t)m * 512 + ka0 + kb + ko;
            float4 v0 = *reinterpret_cast<const float4*>(ap);
            float4 v1 = *reinterpret_cast<const float4*>(ap + 4);
            As[ko+0][m] = v0.x; As[ko+1][m] = v0.y;
            As[ko+2][m] = v0.z; As[ko+3][m] = v0.w;
            As[ko+4][m] = v1.x; As[ko+5][m] = v1.y;
            As[ko+6][m] = v1.z; As[ko+7][m] = v1.w;
        }
        {
#pragma unroll
            for (int it = 0; it < 2; it++) {
                const int kk = (tid >> 5) + it * 8;
                const int c  = (tid & 31) * 4;
                *reinterpret_cast<float4*>(&Bs[kk][c]) =
                    *reinterpret_cast<const float4*>(
                        W + (size_t)(ka0 + kb + kk) * (4 * HDIM) + n0 + c);
            }
        }
        __syncthreads();

#pragma unroll
        for (int kk = 0; kk < KB; kk++) {
            float a[8];
            *reinterpret_cast<float4*>(a)     = *reinterpret_cast<float4*>(&As[kk][ty*8]);
            *reinterpret_cast<float4*>(a + 4) = *reinterpret_cast<float4*>(&As[kk][ty*8+4]);
            ulonglong2 b01 = *reinterpret_cast<ulonglong2*>(&Bs[kk][tx*8]);
            ulonglong2 b23 = *reinterpret_cast<ulonglong2*>(&Bs[kk][tx*8+4]);
            const ull bp0 = b01.x, bp1 = b01.y, bp2 = b23.x, bp3 = b23.y;
#pragma unroll
            for (int i = 0; i < 8; i++) {
                const ull ai = pack2(a[i], a[i]);
                acc2[i][0] = ffma2(ai, bp0, acc2[i][0]);
                acc2[i][1] = ffma2(ai, bp1, acc2[i][1]);
                acc2[i][2] = ffma2(ai, bp2, acc2[i][2]);
                acc2[i][3] = ffma2(ai, bp3, acc2[i][3]);
            }
        }
        __syncthreads();
    }

    float* P = g_part + (size_t)sp * BATCH * (4 * HDIM);
#pragma unroll
    for (int i = 0; i < 8; i++) {
        const int m = ty * 8 + i;
        ulonglong2 w0; w0.x = acc2[i][0]; w0.y = acc2[i][1];
        ulonglong2 w1; w1.x = acc2[i][2]; w1.y = acc2[i][3];
        *reinterpret_cast<ulonglong2*>(&P[(size_t)m * (4*HDIM) + n0 + tx*8])     = w0;
        *reinterpret_cast<ulonglong2*>(&P[(size_t)m * (4*HDIM) + n0 + tx*8 + 4]) = w1;
    }
}

// ---------------------------------------------------------------------------
static void launch_gemm_pdl(const float* W_ih, const float* W_hh,
                            const float* x0, const float* h0, int t)
{
    cudaLaunchAttribute attrs[1];
    attrs[0].id = cudaLaunchAttributeProgrammaticStreamSerialization;
    attrs[0].val.programmaticStreamSerializationAllowed = 1;

    cudaLaunchConfig_t cfg = {};
    cfg.gridDim  = dim3(16, SPLITS);
    cfg.blockDim = dim3(256);
    cfg.dynamicSmemBytes = 0;
    cfg.stream = 0;
    cfg.attrs = attrs;
    cfg.numAttrs = 1;

    cudaLaunchKernelEx(&cfg, gemm_kernel, W_ih, W_hh, x0, h0, t);
}

extern "C" void kernel_launch(void* const* d_in, const int* in_sizes, int n_in,
                              void* d_out, int out_size)
{
    const float* batch  = (const float*)d_in[0];
    const float* hid    = (const float*)d_in[1];
    const float* h0     = (const float*)d_in[2];
    const float* s0     = (const float*)d_in[3];
    const float* W_ih   = (const float*)d_in[4];
    const float* W_hh   = (const float*)d_in[5];
    const float* b_lstm = (const float*)d_in[6];
    const float* W1     = (const float*)d_in[7];
    const float* b1     = (const float*)d_in[8];
    const float* W2     = (const float*)d_in[9];
    const float* b2     = (const float*)d_in[10];
    float* out = (float*)d_out;

    attn0_kernel<<<BATCH, 512>>>(hid, s0);
    launch_gemm_pdl(W_ih, W_hh, batch, h0, 0);

    for (int t = 1; t < TSTEPS; t++) {
        attnC16_kernel<<<BATCH, 512>>>(b_lstm, W1, b1, W2, b2, out, t);
        launch_gemm_pdl(W_ih, W_hh, batch, h0, t);
    }

    combine_tail<<<BATCH, 512>>>(b_lstm, W1, b1, W2, b2, out);
}